// round 3
// baseline (speedup 1.0000x reference)
#include <cuda_runtime.h>
#include <math.h>
#include <stdint.h>

// Problem shape (fixed): B=8, S=2048, D=1024, U=1024, A=4
#define M_TOT 16384   // B*S
#define N_TOT 1024    // U
#define K_TOT 1024    // D
#define A_DIM 4

#define BM 128
#define BN 128
#define BK 16

// Scratch for softmax(x @ w_att + b_att): [M_TOT, 4]
__device__ float g_attn[M_TOT * A_DIM];

// ---------------------------------------------------------------------------
// Kernel A: attention weights. One warp per row.
// ---------------------------------------------------------------------------
__global__ __launch_bounds__(256) void attn_kernel(const float* __restrict__ x,
                                                   const float* __restrict__ w_att,
                                                   const float* __restrict__ b_att) {
    int gtid = blockIdx.x * blockDim.x + threadIdx.x;
    int row  = gtid >> 5;
    int lane = gtid & 31;
    if (row >= M_TOT) return;

    const float*  xr  = x + (size_t)row * K_TOT;
    const float4* wa4 = (const float4*)w_att;   // w_att[k][0..3] contiguous

    float a0 = 0.f, a1 = 0.f, a2 = 0.f, a3 = 0.f;
    for (int k = lane; k < K_TOT; k += 32) {
        float  xv = xr[k];
        float4 wv = wa4[k];
        a0 = fmaf(xv, wv.x, a0);
        a1 = fmaf(xv, wv.y, a1);
        a2 = fmaf(xv, wv.z, a2);
        a3 = fmaf(xv, wv.w, a3);
    }
#pragma unroll
    for (int off = 16; off; off >>= 1) {
        a0 += __shfl_xor_sync(0xffffffffu, a0, off);
        a1 += __shfl_xor_sync(0xffffffffu, a1, off);
        a2 += __shfl_xor_sync(0xffffffffu, a2, off);
        a3 += __shfl_xor_sync(0xffffffffu, a3, off);
    }
    if (lane == 0) {
        a0 += b_att[0]; a1 += b_att[1]; a2 += b_att[2]; a3 += b_att[3];
        float mx = fmaxf(fmaxf(a0, a1), fmaxf(a2, a3));
        float e0 = expf(a0 - mx), e1 = expf(a1 - mx);
        float e2 = expf(a2 - mx), e3 = expf(a3 - mx);
        float inv = 1.f / (e0 + e1 + e2 + e3);
        ((float4*)g_attn)[row] = make_float4(e0 * inv, e1 * inv, e2 * inv, e3 * inv);
    }
}

// ---------------------------------------------------------------------------
// Kernel B: fused GEMM (f32x2 packed FMA) + activation mixture epilogue.
// 256 threads, 128x128x16 tile, 8x8 per-thread microtile.
// ---------------------------------------------------------------------------
__global__ __launch_bounds__(256) void fused_gemm_kernel(
    const float* __restrict__ x,   // [M_TOT, K_TOT]
    const float* __restrict__ w,   // [K_TOT, N_TOT]
    const float* __restrict__ b,   // [N_TOT]
    const float* __restrict__ wf,  // [N_TOT, 4]
    const float* __restrict__ bf,  // [N_TOT, 4]
    float* __restrict__ out)       // [M_TOT, N_TOT]
{
    __shared__ float  As[BK][BM];
    __shared__ float  Bs[BK][BN];
    __shared__ float4 s_attn[BM];
    __shared__ float4 s_wf[BN];
    __shared__ float4 s_bf[BN];
    __shared__ float  s_b[BN];

    const int t  = threadIdx.x;
    const int tx = t & 15;       // column group (8 cols each)
    const int ty = t >> 4;       // row group (8 rows each)
    const int bn = blockIdx.x * BN;
    const int bm = blockIdx.y * BM;

    // Stage epilogue tables
    if (t < BM) {
        s_attn[t] = ((const float4*)g_attn)[bm + t];
    } else {
        int c = t - 128;
        s_wf[c] = ((const float4*)wf)[bn + c];
        s_bf[c] = ((const float4*)bf)[bn + c];
        s_b[c]  = b[bn + c];
    }

    // Accumulators: 8 rows x 4 column-pairs of packed f32x2
    unsigned long long acc[8][4];
#pragma unroll
    for (int i = 0; i < 8; i++)
#pragma unroll
        for (int j = 0; j < 4; j++) acc[i][j] = 0ULL;

    const float4* x4 = (const float4*)x;
    const float4* w4 = (const float4*)w;
    const int Kq = K_TOT / 4;
    const int Nq = N_TOT / 4;

    for (int kt = 0; kt < K_TOT; kt += BK) {
        // Load x tile (128 x 16) -> As transposed [k][m]
#pragma unroll
        for (int i = 0; i < 2; i++) {
            int idx = t + i * 256;           // 0..511
            int row = idx >> 2;              // 0..127
            int c4  = idx & 3;               // 0..3
            float4 v = x4[(size_t)(bm + row) * Kq + (kt >> 2) + c4];
            As[c4 * 4 + 0][row] = v.x;
            As[c4 * 4 + 1][row] = v.y;
            As[c4 * 4 + 2][row] = v.z;
            As[c4 * 4 + 3][row] = v.w;
        }
        // Load w tile (16 x 128) -> Bs [k][n]
#pragma unroll
        for (int i = 0; i < 2; i++) {
            int idx = t + i * 256;           // 0..511
            int row = idx >> 5;              // 0..15
            int c4  = idx & 31;              // 0..31
            float4 v = w4[(size_t)(kt + row) * Nq + (bn >> 2) + c4];
            ((float4*)&Bs[row][0])[c4] = v;
        }
        __syncthreads();

#pragma unroll
        for (int kk = 0; kk < BK; kk++) {
            float a[8];
#pragma unroll
            for (int i = 0; i < 2; i++) {
                float4 av = *(const float4*)&As[kk][ty * 8 + i * 4];
                a[i * 4 + 0] = av.x; a[i * 4 + 1] = av.y;
                a[i * 4 + 2] = av.z; a[i * 4 + 3] = av.w;
            }
            unsigned long long bp[4];
            const unsigned long long* bsu =
                (const unsigned long long*)&Bs[kk][tx * 8];
            bp[0] = bsu[0]; bp[1] = bsu[1]; bp[2] = bsu[2]; bp[3] = bsu[3];
#pragma unroll
            for (int i = 0; i < 8; i++) {
                unsigned int au = __float_as_uint(a[i]);
                unsigned long long ap;
                asm("mov.b64 %0, {%1, %1};" : "=l"(ap) : "r"(au));
#pragma unroll
                for (int j = 0; j < 4; j++) {
                    asm("fma.rn.f32x2 %0, %1, %2, %0;"
                        : "+l"(acc[i][j]) : "l"(ap), "l"(bp[j]));
                }
            }
        }
        __syncthreads();
    }

    // Epilogue: ws -> per-activation affine -> 4 activations -> attn-weighted sum
    const float inv_sqrt2 = 0.70710678118654752f;
#pragma unroll
    for (int i = 0; i < 8; i++) {
        int    lr = ty * 8 + i;
        int    gr = bm + lr;
        float4 at = s_attn[lr];
        float  res[8];
#pragma unroll
        for (int j = 0; j < 4; j++) {
            unsigned int lo_u, hi_u;
            asm("mov.b64 {%0, %1}, %2;" : "=r"(lo_u), "=r"(hi_u) : "l"(acc[i][j]));
            float v2[2] = { __uint_as_float(lo_u), __uint_as_float(hi_u) };
#pragma unroll
            for (int h = 0; h < 2; h++) {
                int    lc  = tx * 8 + j * 2 + h;
                float  s   = v2[h] + s_b[lc];
                float4 wfv = s_wf[lc];
                float4 bfv = s_bf[lc];
                float z0 = fmaf(s, wfv.x, bfv.x);
                float z1 = fmaf(s, wfv.y, bfv.y);
                float z2 = fmaf(s, wfv.z, bfv.z);
                float z3 = fmaf(s, wfv.w, bfv.w);
                float r0 = fmaxf(z0, 0.f);
                float r1 = 1.f / (1.f + expf(-z1));
                float r2 = tanhf(z2);
                float r3 = 0.5f * z3 * (1.f + erff(z3 * inv_sqrt2));
                res[j * 2 + h] = r0 * at.x + r1 * at.y + r2 * at.z + r3 * at.w;
            }
        }
        float4* o4 = (float4*)(out + (size_t)gr * N_TOT + bn + tx * 8);
        o4[0] = make_float4(res[0], res[1], res[2], res[3]);
        o4[1] = make_float4(res[4], res[5], res[6], res[7]);
    }
}

// ---------------------------------------------------------------------------
extern "C" void kernel_launch(void* const* d_in, const int* in_sizes, int n_in,
                              void* d_out, int out_size) {
    const float* x     = (const float*)d_in[0];
    const float* w     = (const float*)d_in[1];
    const float* b     = (const float*)d_in[2];
    const float* wf    = (const float*)d_in[3];
    const float* bf    = (const float*)d_in[4];
    const float* w_att = (const float*)d_in[5];
    const float* b_att = (const float*)d_in[6];
    float* out = (float*)d_out;

    // Kernel A: attention weights (one warp per row, 8 warps/block)
    attn_kernel<<<(M_TOT * 32) / 256, 256>>>(x, w_att, b_att);

    // Kernel B: fused GEMM + epilogue
    dim3 grid(N_TOT / BN, M_TOT / BM);  // (8, 128)
    fused_gemm_kernel<<<grid, 256>>>(x, w, b, wf, bf, out);
}

// round 6
// speedup vs baseline: 1.9760x; 1.9760x over previous
#include <cuda_runtime.h>
#include <cuda_bf16.h>
#include <math.h>
#include <stdint.h>

// Shape (fixed): B=8, S=2048, D=1024, U=1024, A=4
#define M_TOT 16384
#define N_TOT 1024
#define K_TOT 1024

// GEMM tiling (mma.sync HMMA path; tcgen05 unavailable at compute_103 base)
#define BM 256
#define BN 128
#define BKC 32            // bf16 K elems per stage chunk
#define NSTAGE 4
#define NITER 96          // 3 split terms * (1024/32)

// SMEM stage layout: padded rows for conflict-free ldmatrix
#define LDA 40            // A row stride in bf16 elems (80 B)
#define LDB 136           // B row stride in bf16 elems (272 B)
#define STAGE_A_BYTES (BM * LDA * 2)      // 20480
#define STAGE_B_BYTES (BKC * LDB * 2)     // 8704
#define STAGE_BYTES   (STAGE_A_BYTES + STAGE_B_BYTES)   // 29184
#define SM_ATTN  0                         // 256 * float4 = 4096
#define SM_B     4096                      // 128 * float  = 512
#define SM_WF    4608                      // 128 * float4 = 2048
#define SM_BF    6656                      // 128 * float4 = 2048
#define SM_STAGE 8704
#define SM_TOTAL (SM_STAGE + NSTAGE * STAGE_BYTES)      // 125440

// ---------------- scratch (device globals; no allocation allowed) ----------
__device__ __nv_bfloat16 g_xh[(size_t)M_TOT * K_TOT];
__device__ __nv_bfloat16 g_xl[(size_t)M_TOT * K_TOT];
__device__ __nv_bfloat16 g_wh[(size_t)K_TOT * N_TOT];   // w hi, [K][N]
__device__ __nv_bfloat16 g_wl[(size_t)K_TOT * N_TOT];   // w lo, [K][N]
__device__ float g_attn[(size_t)M_TOT * 4];

// ---------------- helpers ---------------------------------------------------
__device__ __forceinline__ uint32_t smem_u32(const void* p) {
    return (uint32_t)__cvta_generic_to_shared(p);
}
__device__ __forceinline__ void cp16(uint32_t s, const void* g) {
    asm volatile("cp.async.cg.shared.global [%0], [%1], 16;" :: "r"(s), "l"(g));
}
__device__ __forceinline__ void cp_commit() {
    asm volatile("cp.async.commit_group;" ::: "memory");
}
__device__ __forceinline__ void cp_wait2() {
    asm volatile("cp.async.wait_group 2;" ::: "memory");
}
__device__ __forceinline__ void ldsm_x4(uint32_t* r, uint32_t a) {
    asm volatile("ldmatrix.sync.aligned.m8n8.x4.shared.b16 {%0,%1,%2,%3}, [%4];"
                 : "=r"(r[0]), "=r"(r[1]), "=r"(r[2]), "=r"(r[3]) : "r"(a));
}
__device__ __forceinline__ void ldsm_x4_t(uint32_t* r, uint32_t a) {
    asm volatile("ldmatrix.sync.aligned.m8n8.x4.trans.shared.b16 {%0,%1,%2,%3}, [%4];"
                 : "=r"(r[0]), "=r"(r[1]), "=r"(r[2]), "=r"(r[3]) : "r"(a));
}
__device__ __forceinline__ void mma_bf16(float* c, const uint32_t* a,
                                         uint32_t b0, uint32_t b1) {
    asm volatile(
        "mma.sync.aligned.m16n8k16.row.col.f32.bf16.bf16.f32 "
        "{%0,%1,%2,%3}, {%4,%5,%6,%7}, {%8,%9}, {%0,%1,%2,%3};"
        : "+f"(c[0]), "+f"(c[1]), "+f"(c[2]), "+f"(c[3])
        : "r"(a[0]), "r"(a[1]), "r"(a[2]), "r"(a[3]), "r"(b0), "r"(b1));
}
__device__ __forceinline__ unsigned short bf_hi_lo(float v, unsigned short& lo) {
    __nv_bfloat16 h = __float2bfloat16(v);
    float hf = __bfloat162float(h);
    __nv_bfloat16 l = __float2bfloat16(v - hf);
    lo = __bfloat16_as_ushort(l);
    return __bfloat16_as_ushort(h);
}

// ---------------------------------------------------------------------------
// Prep 1: fused attention softmax + x -> (x_hi, x_lo) bf16 split. x read once.
// ---------------------------------------------------------------------------
__global__ __launch_bounds__(256) void prep_x_attn(const float* __restrict__ x,
                                                   const float* __restrict__ w_att,
                                                   const float* __restrict__ b_att) {
    int row  = blockIdx.x * 8 + (threadIdx.x >> 5);
    int lane = threadIdx.x & 31;
    const float4* x4  = (const float4*)x;
    const float4* wa4 = (const float4*)w_att;

    float a0 = 0.f, a1 = 0.f, a2 = 0.f, a3 = 0.f;
#pragma unroll
    for (int i = 0; i < 8; i++) {
        int q = i * 32 + lane;
        float4 v = x4[(size_t)row * 256 + q];
        float4 w0 = wa4[q * 4 + 0], w1 = wa4[q * 4 + 1];
        float4 w2 = wa4[q * 4 + 2], w3 = wa4[q * 4 + 3];
        a0 = fmaf(v.x, w0.x, fmaf(v.y, w1.x, fmaf(v.z, w2.x, fmaf(v.w, w3.x, a0))));
        a1 = fmaf(v.x, w0.y, fmaf(v.y, w1.y, fmaf(v.z, w2.y, fmaf(v.w, w3.y, a1))));
        a2 = fmaf(v.x, w0.z, fmaf(v.y, w1.z, fmaf(v.z, w2.z, fmaf(v.w, w3.z, a2))));
        a3 = fmaf(v.x, w0.w, fmaf(v.y, w1.w, fmaf(v.z, w2.w, fmaf(v.w, w3.w, a3))));

        unsigned short l0, l1, l2, l3;
        unsigned short h0 = bf_hi_lo(v.x, l0), h1 = bf_hi_lo(v.y, l1);
        unsigned short h2 = bf_hi_lo(v.z, l2), h3 = bf_hi_lo(v.w, l3);
        ((uint2*)g_xh)[(size_t)row * 256 + q] =
            make_uint2((uint32_t)h0 | ((uint32_t)h1 << 16),
                       (uint32_t)h2 | ((uint32_t)h3 << 16));
        ((uint2*)g_xl)[(size_t)row * 256 + q] =
            make_uint2((uint32_t)l0 | ((uint32_t)l1 << 16),
                       (uint32_t)l2 | ((uint32_t)l3 << 16));
    }
#pragma unroll
    for (int off = 16; off; off >>= 1) {
        a0 += __shfl_xor_sync(0xffffffffu, a0, off);
        a1 += __shfl_xor_sync(0xffffffffu, a1, off);
        a2 += __shfl_xor_sync(0xffffffffu, a2, off);
        a3 += __shfl_xor_sync(0xffffffffu, a3, off);
    }
    if (lane == 0) {
        a0 += b_att[0]; a1 += b_att[1]; a2 += b_att[2]; a3 += b_att[3];
        float mx = fmaxf(fmaxf(a0, a1), fmaxf(a2, a3));
        float e0 = expf(a0 - mx), e1 = expf(a1 - mx);
        float e2 = expf(a2 - mx), e3 = expf(a3 - mx);
        float inv = 1.f / (e0 + e1 + e2 + e3);
        ((float4*)g_attn)[row] = make_float4(e0 * inv, e1 * inv, e2 * inv, e3 * inv);
    }
}

// ---------------------------------------------------------------------------
// Prep 2: w [K][N] f32 -> hi/lo bf16, same layout (elementwise)
// ---------------------------------------------------------------------------
__global__ __launch_bounds__(256) void prep_w(const float* __restrict__ w) {
    int i = blockIdx.x * 256 + threadIdx.x;   // float4 index; total 262144
    float4 v = ((const float4*)w)[i];
    unsigned short l0, l1, l2, l3;
    unsigned short h0 = bf_hi_lo(v.x, l0), h1 = bf_hi_lo(v.y, l1);
    unsigned short h2 = bf_hi_lo(v.z, l2), h3 = bf_hi_lo(v.w, l3);
    ((uint2*)g_wh)[i] = make_uint2((uint32_t)h0 | ((uint32_t)h1 << 16),
                                   (uint32_t)h2 | ((uint32_t)h3 << 16));
    ((uint2*)g_wl)[i] = make_uint2((uint32_t)l0 | ((uint32_t)l1 << 16),
                                   (uint32_t)l2 | ((uint32_t)l3 << 16));
}

// ---------------------------------------------------------------------------
// Main fused GEMM: bf16 mma.sync 3-term split + activation/attention epilogue.
// 512 threads, 256x128 tile, 16 warps (8x2), warp tile 32x64.
// ---------------------------------------------------------------------------
__device__ __forceinline__ void issue_stage(char* smem, int idx, int t,
                                            int bm, int bn) {
    int term = idx >> 5;
    int kt   = (idx & 31) * BKC;
    const __nv_bfloat16* Ab = (term == 1) ? g_xl : g_xh;
    const __nv_bfloat16* Bb = (term == 2) ? g_wl : g_wh;
    char* A = smem + SM_STAGE + (idx % NSTAGE) * STAGE_BYTES;
    char* B = A + STAGE_A_BYTES;
    // A: 256 rows x 4 chunks(16B) = 1024 chunks, 2 per thread
#pragma unroll
    for (int i = 0; i < 2; i++) {
        int id  = t + i * 512;
        int row = id >> 2, cq = id & 3;
        cp16(smem_u32(A + row * (LDA * 2) + cq * 16),
             Ab + (size_t)(bm + row) * K_TOT + kt + cq * 8);
    }
    // B: 32 rows x 16 chunks = 512 chunks, 1 per thread
    {
        int row = t >> 4, cq = t & 15;
        cp16(smem_u32(B + row * (LDB * 2) + cq * 16),
             Bb + (size_t)(kt + row) * N_TOT + bn + cq * 8);
    }
    cp_commit();
}

__global__ __launch_bounds__(512, 1)
void fused_gemm_hmma(const float* __restrict__ b,
                     const float* __restrict__ wf,
                     const float* __restrict__ bf,
                     float* __restrict__ out) {
    extern __shared__ char smem[];
    const int t    = threadIdx.x;
    const int wid  = t >> 5;
    const int lane = t & 31;
    const int bm   = blockIdx.y * BM;
    const int bn   = blockIdx.x * BN;
    const int m0   = (wid >> 1) * 32;    // warp M offset in tile
    const int n0   = (wid & 1) * 64;     // warp N offset in tile

    // Stage epilogue tables (512 threads)
    if (t < 256) ((float4*)(smem + SM_ATTN))[t] = ((const float4*)g_attn)[bm + t];
    else {
        int c = t - 256;
        if (c < 128) {
            ((float*)(smem + SM_B))[c]   = b[bn + c];
            ((float4*)(smem + SM_WF))[c] = ((const float4*)wf)[bn + c];
            ((float4*)(smem + SM_BF))[c] = ((const float4*)bf)[bn + c];
        }
    }

    issue_stage(smem, 0, t, bm, bn);
    issue_stage(smem, 1, t, bm, bn);
    issue_stage(smem, 2, t, bm, bn);

    float c[2][8][4];
#pragma unroll
    for (int mt = 0; mt < 2; mt++)
#pragma unroll
        for (int nt = 0; nt < 8; nt++)
#pragma unroll
            for (int r = 0; r < 4; r++) c[mt][nt][r] = 0.f;

    const int lrow = lane & 15;
    const int lcol = (lane >> 4) * 8;

    for (int i = 0; i < NITER; i++) {
        cp_wait2();
        __syncthreads();
        if (i + 3 < NITER) issue_stage(smem, i + 3, t, bm, bn);

        char* A = smem + SM_STAGE + (i % NSTAGE) * STAGE_BYTES;
        char* B = A + STAGE_A_BYTES;
#pragma unroll
        for (int k0 = 0; k0 < BKC; k0 += 16) {
            uint32_t af[2][4], bb[4][4];
#pragma unroll
            for (int mt = 0; mt < 2; mt++)
                ldsm_x4(af[mt], smem_u32(A + ((m0 + mt * 16 + lrow) * LDA
                                              + k0 + lcol) * 2));
#pragma unroll
            for (int ng = 0; ng < 4; ng++)
                ldsm_x4_t(bb[ng], smem_u32(B + ((k0 + lrow) * LDB
                                                + n0 + ng * 16 + lcol) * 2));
#pragma unroll
            for (int mt = 0; mt < 2; mt++)
#pragma unroll
                for (int nt = 0; nt < 8; nt++)
                    mma_bf16(c[mt][nt], af[mt],
                             bb[nt >> 1][(nt & 1) * 2], bb[nt >> 1][(nt & 1) * 2 + 1]);
        }
        __syncthreads();
    }

    // Epilogue: bias -> per-activation affine -> activations -> attn mix
    const float*  sB  = (const float*)(smem + SM_B);
    const float4* sWF = (const float4*)(smem + SM_WF);
    const float4* sBF = (const float4*)(smem + SM_BF);
    const float4* sAT = (const float4*)(smem + SM_ATTN);
    const float inv_sqrt2 = 0.70710678118654752f;

#pragma unroll
    for (int mt = 0; mt < 2; mt++) {
#pragma unroll
        for (int half = 0; half < 2; half++) {
            int lr = m0 + mt * 16 + (lane >> 2) + half * 8;
            float4 at = sAT[lr];
            float* orow = out + (size_t)(bm + lr) * N_TOT + bn;
#pragma unroll
            for (int nt = 0; nt < 8; nt++) {
                int col0 = n0 + nt * 8 + (lane & 3) * 2;
                float2 res;
#pragma unroll
                for (int h = 0; h < 2; h++) {
                    int col = col0 + h;
                    float s = c[mt][nt][half * 2 + h] + sB[col];
                    float4 wfv = sWF[col];
                    float4 bfv = sBF[col];
                    float z0 = fmaf(s, wfv.x, bfv.x);
                    float z1 = fmaf(s, wfv.y, bfv.y);
                    float z2 = fmaf(s, wfv.z, bfv.z);
                    float z3 = fmaf(s, wfv.w, bfv.w);
                    float r0 = fmaxf(z0, 0.f);
                    float r1 = __fdividef(1.f, 1.f + __expf(-z1));
                    float r2 = 1.f - __fdividef(2.f, __expf(2.f * z2) + 1.f);
                    float r3 = 0.5f * z3 * (1.f + erff(z3 * inv_sqrt2));
                    float v = r0 * at.x + r1 * at.y + r2 * at.z + r3 * at.w;
                    if (h == 0) res.x = v; else res.y = v;
                }
                *(float2*)(orow + col0) = res;
            }
        }
    }
}

// ---------------------------------------------------------------------------
extern "C" void kernel_launch(void* const* d_in, const int* in_sizes, int n_in,
                              void* d_out, int out_size) {
    const float* x     = (const float*)d_in[0];
    const float* w     = (const float*)d_in[1];
    const float* b     = (const float*)d_in[2];
    const float* wf    = (const float*)d_in[3];
    const float* bf    = (const float*)d_in[4];
    const float* w_att = (const float*)d_in[5];
    const float* b_att = (const float*)d_in[6];
    float* out = (float*)d_out;

    static int configured = 0;
    if (!configured) {
        cudaFuncSetAttribute(fused_gemm_hmma,
                             cudaFuncAttributeMaxDynamicSharedMemorySize, SM_TOTAL);
        configured = 1;
    }

    prep_x_attn<<<M_TOT / 8, 256>>>(x, w_att, b_att);
    prep_w<<<(K_TOT * N_TOT / 4) / 256, 256>>>(w);
    fused_gemm_hmma<<<dim3(N_TOT / BN, M_TOT / BM), 512, SM_TOTAL>>>(b, wf, bf, out);
}

// round 7
// speedup vs baseline: 3.1057x; 1.5717x over previous
#include <cuda_runtime.h>
#include <cuda_fp16.h>
#include <math.h>
#include <stdint.h>

// Shape (fixed): B=8, S=2048, D=1024, U=1024, A=4
#define M_TOT 16384
#define N_TOT 1024
#define K_TOT 1024

// GEMM tiling: fp16 mma.sync, 2-term split (xh*w + xl*w), 2 CTAs/SM
#define BM 128
#define BN 128
#define BKC 32            // fp16 K elems per stage chunk
#define NSTAGE 4
#define NITER 64          // 2 split terms * (1024/32)

// SMEM stage layout: padded rows for conflict-free ldmatrix
#define LDA 40            // A row stride in fp16 elems (80 B)
#define LDB 136           // B row stride in fp16 elems (272 B)
#define STAGE_A_BYTES (BM * LDA * 2)      // 10240
#define STAGE_B_BYTES (BKC * LDB * 2)     // 8704
#define STAGE_BYTES   (STAGE_A_BYTES + STAGE_B_BYTES)   // 18944
#define SM_ATTN  0                         // 128 * float4 = 2048
#define SM_B     2048                      // 128 * float  = 512
#define SM_WF    2560                      // 128 * float4 = 2048
#define SM_BF    4608                      // 128 * float4 = 2048
#define SM_STAGE 6656
#define SM_TOTAL (SM_STAGE + NSTAGE * STAGE_BYTES)      // 82432 (x2 CTAs fits 228KB)

// ---------------- scratch (device globals; no allocation allowed) ----------
__device__ __half g_xh[(size_t)M_TOT * K_TOT];
__device__ __half g_xl[(size_t)M_TOT * K_TOT];
__device__ __half g_wh[(size_t)K_TOT * N_TOT];   // w fp16, [K][N]
__device__ float g_attn[(size_t)M_TOT * 4];

// ---------------- helpers ---------------------------------------------------
__device__ __forceinline__ uint32_t smem_u32(const void* p) {
    return (uint32_t)__cvta_generic_to_shared(p);
}
__device__ __forceinline__ void cp16(uint32_t s, const void* g) {
    asm volatile("cp.async.cg.shared.global [%0], [%1], 16;" :: "r"(s), "l"(g));
}
__device__ __forceinline__ void cp_commit() {
    asm volatile("cp.async.commit_group;" ::: "memory");
}
__device__ __forceinline__ void cp_wait2() {
    asm volatile("cp.async.wait_group 2;" ::: "memory");
}
__device__ __forceinline__ void ldsm_x4(uint32_t* r, uint32_t a) {
    asm volatile("ldmatrix.sync.aligned.m8n8.x4.shared.b16 {%0,%1,%2,%3}, [%4];"
                 : "=r"(r[0]), "=r"(r[1]), "=r"(r[2]), "=r"(r[3]) : "r"(a));
}
__device__ __forceinline__ void ldsm_x4_t(uint32_t* r, uint32_t a) {
    asm volatile("ldmatrix.sync.aligned.m8n8.x4.trans.shared.b16 {%0,%1,%2,%3}, [%4];"
                 : "=r"(r[0]), "=r"(r[1]), "=r"(r[2]), "=r"(r[3]) : "r"(a));
}
__device__ __forceinline__ void mma_fp16(float* c, const uint32_t* a,
                                         uint32_t b0, uint32_t b1) {
    asm volatile(
        "mma.sync.aligned.m16n8k16.row.col.f32.f16.f16.f32 "
        "{%0,%1,%2,%3}, {%4,%5,%6,%7}, {%8,%9}, {%0,%1,%2,%3};"
        : "+f"(c[0]), "+f"(c[1]), "+f"(c[2]), "+f"(c[3])
        : "r"(a[0]), "r"(a[1]), "r"(a[2]), "r"(a[3]), "r"(b0), "r"(b1));
}
__device__ __forceinline__ unsigned short h_hi_lo(float v, unsigned short& lo) {
    __half h = __float2half_rn(v);
    float hf = __half2float(h);
    lo = __half_as_ushort(__float2half_rn(v - hf));
    return __half_as_ushort(h);
}

// ---------------------------------------------------------------------------
// Prep 1: fused attention softmax + x -> (x_hi, x_lo) fp16 split. x read once.
// ---------------------------------------------------------------------------
__global__ __launch_bounds__(256) void prep_x_attn(const float* __restrict__ x,
                                                   const float* __restrict__ w_att,
                                                   const float* __restrict__ b_att) {
    int row  = blockIdx.x * 8 + (threadIdx.x >> 5);
    int lane = threadIdx.x & 31;
    const float4* x4  = (const float4*)x;
    const float4* wa4 = (const float4*)w_att;

    float a0 = 0.f, a1 = 0.f, a2 = 0.f, a3 = 0.f;
#pragma unroll
    for (int i = 0; i < 8; i++) {
        int q = i * 32 + lane;
        float4 v = x4[(size_t)row * 256 + q];
        float4 w0 = wa4[q * 4 + 0], w1 = wa4[q * 4 + 1];
        float4 w2 = wa4[q * 4 + 2], w3 = wa4[q * 4 + 3];
        a0 = fmaf(v.x, w0.x, fmaf(v.y, w1.x, fmaf(v.z, w2.x, fmaf(v.w, w3.x, a0))));
        a1 = fmaf(v.x, w0.y, fmaf(v.y, w1.y, fmaf(v.z, w2.y, fmaf(v.w, w3.y, a1))));
        a2 = fmaf(v.x, w0.z, fmaf(v.y, w1.z, fmaf(v.z, w2.z, fmaf(v.w, w3.z, a2))));
        a3 = fmaf(v.x, w0.w, fmaf(v.y, w1.w, fmaf(v.z, w2.w, fmaf(v.w, w3.w, a3))));

        unsigned short l0, l1, l2, l3;
        unsigned short h0 = h_hi_lo(v.x, l0), h1 = h_hi_lo(v.y, l1);
        unsigned short h2 = h_hi_lo(v.z, l2), h3 = h_hi_lo(v.w, l3);
        ((uint2*)g_xh)[(size_t)row * 256 + q] =
            make_uint2((uint32_t)h0 | ((uint32_t)h1 << 16),
                       (uint32_t)h2 | ((uint32_t)h3 << 16));
        ((uint2*)g_xl)[(size_t)row * 256 + q] =
            make_uint2((uint32_t)l0 | ((uint32_t)l1 << 16),
                       (uint32_t)l2 | ((uint32_t)l3 << 16));
    }
#pragma unroll
    for (int off = 16; off; off >>= 1) {
        a0 += __shfl_xor_sync(0xffffffffu, a0, off);
        a1 += __shfl_xor_sync(0xffffffffu, a1, off);
        a2 += __shfl_xor_sync(0xffffffffu, a2, off);
        a3 += __shfl_xor_sync(0xffffffffu, a3, off);
    }
    if (lane == 0) {
        a0 += b_att[0]; a1 += b_att[1]; a2 += b_att[2]; a3 += b_att[3];
        float mx = fmaxf(fmaxf(a0, a1), fmaxf(a2, a3));
        float e0 = expf(a0 - mx), e1 = expf(a1 - mx);
        float e2 = expf(a2 - mx), e3 = expf(a3 - mx);
        float inv = 1.f / (e0 + e1 + e2 + e3);
        ((float4*)g_attn)[row] = make_float4(e0 * inv, e1 * inv, e2 * inv, e3 * inv);
    }
}

// ---------------------------------------------------------------------------
// Prep 2: w [K][N] f32 -> fp16, same layout (elementwise)
// ---------------------------------------------------------------------------
__global__ __launch_bounds__(256) void prep_w(const float* __restrict__ w) {
    int i = blockIdx.x * 256 + threadIdx.x;   // float4 index; total 262144
    float4 v = ((const float4*)w)[i];
    unsigned short h0 = __half_as_ushort(__float2half_rn(v.x));
    unsigned short h1 = __half_as_ushort(__float2half_rn(v.y));
    unsigned short h2 = __half_as_ushort(__float2half_rn(v.z));
    unsigned short h3 = __half_as_ushort(__float2half_rn(v.w));
    ((uint2*)g_wh)[i] = make_uint2((uint32_t)h0 | ((uint32_t)h1 << 16),
                                   (uint32_t)h2 | ((uint32_t)h3 << 16));
}

// ---------------------------------------------------------------------------
// Main fused GEMM: fp16 mma.sync 2-term split + activation/attention epilogue.
// 256 threads, 128x128 tile, 8 warps (4x2), warp tile 32x64, 2 CTAs/SM.
// ---------------------------------------------------------------------------
__device__ __forceinline__ void issue_stage(char* smem, int idx, int t,
                                            int bm, int bn) {
    int term = idx >> 5;
    int kt   = (idx & 31) * BKC;
    const __half* Ab = term ? g_xl : g_xh;
    char* A = smem + SM_STAGE + (idx % NSTAGE) * STAGE_BYTES;
    char* B = A + STAGE_A_BYTES;
    // A: 128 rows x 4 chunks(16B) = 512 chunks, 2 per thread
#pragma unroll
    for (int i = 0; i < 2; i++) {
        int id  = t + i * 256;
        int row = id >> 2, cq = id & 3;
        cp16(smem_u32(A + row * (LDA * 2) + cq * 16),
             Ab + (size_t)(bm + row) * K_TOT + kt + cq * 8);
    }
    // B: 32 rows x 16 chunks = 512 chunks, 2 per thread
#pragma unroll
    for (int i = 0; i < 2; i++) {
        int id  = t + i * 256;
        int row = id >> 4, cq = id & 15;
        cp16(smem_u32(B + row * (LDB * 2) + cq * 16),
             g_wh + (size_t)(kt + row) * N_TOT + bn + cq * 8);
    }
    cp_commit();
}

__global__ __launch_bounds__(256, 2)
void fused_gemm_hmma(const float* __restrict__ b,
                     const float* __restrict__ wf,
                     const float* __restrict__ bf,
                     float* __restrict__ out) {
    extern __shared__ char smem[];
    const int t    = threadIdx.x;
    const int wid  = t >> 5;
    const int lane = t & 31;
    const int bm   = blockIdx.y * BM;
    const int bn   = blockIdx.x * BN;
    const int m0   = (wid >> 1) * 32;    // warp M offset in tile
    const int n0   = (wid & 1) * 64;     // warp N offset in tile

    // Stage epilogue tables (256 threads)
    if (t < 128) {
        ((float4*)(smem + SM_ATTN))[t] = ((const float4*)g_attn)[bm + t];
    } else {
        int c = t - 128;
        ((float*)(smem + SM_B))[c]   = b[bn + c];
        ((float4*)(smem + SM_WF))[c] = ((const float4*)wf)[bn + c];
        ((float4*)(smem + SM_BF))[c] = ((const float4*)bf)[bn + c];
    }

    issue_stage(smem, 0, t, bm, bn);
    issue_stage(smem, 1, t, bm, bn);
    issue_stage(smem, 2, t, bm, bn);

    float c[2][8][4];
#pragma unroll
    for (int mt = 0; mt < 2; mt++)
#pragma unroll
        for (int nt = 0; nt < 8; nt++)
#pragma unroll
            for (int r = 0; r < 4; r++) c[mt][nt][r] = 0.f;

    const int lrow = lane & 15;
    const int lcol = (lane >> 4) * 8;

    for (int i = 0; i < NITER; i++) {
        cp_wait2();
        __syncthreads();   // stage i ready AND everyone done reading slot (i+3)%4
        if (i + 3 < NITER) issue_stage(smem, i + 3, t, bm, bn);

        char* A = smem + SM_STAGE + (i % NSTAGE) * STAGE_BYTES;
        char* B = A + STAGE_A_BYTES;
#pragma unroll
        for (int k0 = 0; k0 < BKC; k0 += 16) {
            uint32_t af[2][4], bb[4][4];
#pragma unroll
            for (int mt = 0; mt < 2; mt++)
                ldsm_x4(af[mt], smem_u32(A + ((m0 + mt * 16 + lrow) * LDA
                                              + k0 + lcol) * 2));
#pragma unroll
            for (int ng = 0; ng < 4; ng++)
                ldsm_x4_t(bb[ng], smem_u32(B + ((k0 + lrow) * LDB
                                                + n0 + ng * 16 + lcol) * 2));
#pragma unroll
            for (int mt = 0; mt < 2; mt++)
#pragma unroll
                for (int nt = 0; nt < 8; nt++)
                    mma_fp16(c[mt][nt], af[mt],
                             bb[nt >> 1][(nt & 1) * 2], bb[nt >> 1][(nt & 1) * 2 + 1]);
        }
    }
    __syncthreads();

    // Epilogue: bias -> per-activation affine -> activations -> attn mix
    const float*  sB  = (const float*)(smem + SM_B);
    const float4* sWF = (const float4*)(smem + SM_WF);
    const float4* sBF = (const float4*)(smem + SM_BF);
    const float4* sAT = (const float4*)(smem + SM_ATTN);
    const float inv_sqrt2 = 0.70710678118654752f;

#pragma unroll
    for (int mt = 0; mt < 2; mt++) {
#pragma unroll
        for (int half = 0; half < 2; half++) {
            int lr = m0 + mt * 16 + (lane >> 2) + half * 8;
            float4 at = sAT[lr];
            float* orow = out + (size_t)(bm + lr) * N_TOT + bn;
#pragma unroll
            for (int nt = 0; nt < 8; nt++) {
                int col0 = n0 + nt * 8 + (lane & 3) * 2;
                float2 res;
#pragma unroll
                for (int h = 0; h < 2; h++) {
                    int col = col0 + h;
                    float s = c[mt][nt][half * 2 + h] + sB[col];
                    float4 wfv = sWF[col];
                    float4 bfv = sBF[col];
                    float z0 = fmaf(s, wfv.x, bfv.x);
                    float z1 = fmaf(s, wfv.y, bfv.y);
                    float z2 = fmaf(s, wfv.z, bfv.z);
                    float z3 = fmaf(s, wfv.w, bfv.w);
                    float r0 = fmaxf(z0, 0.f);
                    float r1 = __fdividef(1.f, 1.f + __expf(-z1));
                    float r2 = 1.f - __fdividef(2.f, __expf(2.f * z2) + 1.f);
                    float r3 = 0.5f * z3 * (1.f + erff(z3 * inv_sqrt2));
                    float v = r0 * at.x + r1 * at.y + r2 * at.z + r3 * at.w;
                    if (h == 0) res.x = v; else res.y = v;
                }
                *(float2*)(orow + col0) = res;
            }
        }
    }
}

// ---------------------------------------------------------------------------
extern "C" void kernel_launch(void* const* d_in, const int* in_sizes, int n_in,
                              void* d_out, int out_size) {
    const float* x     = (const float*)d_in[0];
    const float* w     = (const float*)d_in[1];
    const float* b     = (const float*)d_in[2];
    const float* wf    = (const float*)d_in[3];
    const float* bf    = (const float*)d_in[4];
    const float* w_att = (const float*)d_in[5];
    const float* b_att = (const float*)d_in[6];
    float* out = (float*)d_out;

    cudaFuncSetAttribute(fused_gemm_hmma,
                         cudaFuncAttributeMaxDynamicSharedMemorySize, SM_TOTAL);

    prep_x_attn<<<M_TOT / 8, 256>>>(x, w_att, b_att);
    prep_w<<<(K_TOT * N_TOT / 4) / 256, 256>>>(w);
    fused_gemm_hmma<<<dim3(N_TOT / BN, M_TOT / BM), 256, SM_TOTAL>>>(b, wf, bf, out);
}

// round 8
// speedup vs baseline: 4.9499x; 1.5938x over previous
#include <cuda_runtime.h>
#include <cuda_fp16.h>
#include <math.h>
#include <stdint.h>

// Shape (fixed): B=8, S=2048, D=1024, U=1024, A=4
#define M_TOT 16384
#define N_TOT 1024
#define K_TOT 1024

// GEMM tiling: fp16 mma.sync, SINGLE term (x_fp16 * w_fp16), 2 CTAs/SM
#define BM 128
#define BN 128
#define BKC 32            // fp16 K elems per stage chunk
#define NSTAGE 4
#define NITER 32          // 1024/32

// SMEM stage layout: padded rows for conflict-free ldmatrix
#define LDA 40            // A row stride in fp16 elems (80 B)
#define LDB 136           // B row stride in fp16 elems (272 B)
#define STAGE_A_BYTES (BM * LDA * 2)      // 10240
#define STAGE_B_BYTES (BKC * LDB * 2)     // 8704
#define STAGE_BYTES   (STAGE_A_BYTES + STAGE_B_BYTES)   // 18944
#define SM_ATTN  0                         // 128 * float4 = 2048
#define SM_B     2048                      // 128 * float  = 512
#define SM_WF    2560                      // 128 * float4 = 2048
#define SM_BF    4608                      // 128 * float4 = 2048
#define SM_STAGE 6656
#define SM_TOTAL (SM_STAGE + NSTAGE * STAGE_BYTES)      // 82432 (2 CTAs/SM)

// ---------------- scratch (device globals; no allocation allowed) ----------
__device__ __half g_xh[(size_t)M_TOT * K_TOT];
__device__ __half g_wh[(size_t)K_TOT * N_TOT];   // w fp16, [K][N]
__device__ float g_attn[(size_t)M_TOT * 4];

// ---------------- helpers ---------------------------------------------------
__device__ __forceinline__ uint32_t smem_u32(const void* p) {
    return (uint32_t)__cvta_generic_to_shared(p);
}
__device__ __forceinline__ void cp16(uint32_t s, const void* g) {
    asm volatile("cp.async.cg.shared.global [%0], [%1], 16;" :: "r"(s), "l"(g));
}
__device__ __forceinline__ void cp_commit() {
    asm volatile("cp.async.commit_group;" ::: "memory");
}
__device__ __forceinline__ void cp_wait2() {
    asm volatile("cp.async.wait_group 2;" ::: "memory");
}
__device__ __forceinline__ void ldsm_x4(uint32_t* r, uint32_t a) {
    asm volatile("ldmatrix.sync.aligned.m8n8.x4.shared.b16 {%0,%1,%2,%3}, [%4];"
                 : "=r"(r[0]), "=r"(r[1]), "=r"(r[2]), "=r"(r[3]) : "r"(a));
}
__device__ __forceinline__ void ldsm_x4_t(uint32_t* r, uint32_t a) {
    asm volatile("ldmatrix.sync.aligned.m8n8.x4.trans.shared.b16 {%0,%1,%2,%3}, [%4];"
                 : "=r"(r[0]), "=r"(r[1]), "=r"(r[2]), "=r"(r[3]) : "r"(a));
}
__device__ __forceinline__ void mma_fp16(float* c, const uint32_t* a,
                                         uint32_t b0, uint32_t b1) {
    asm volatile(
        "mma.sync.aligned.m16n8k16.row.col.f32.f16.f16.f32 "
        "{%0,%1,%2,%3}, {%4,%5,%6,%7}, {%8,%9}, {%0,%1,%2,%3};"
        : "+f"(c[0]), "+f"(c[1]), "+f"(c[2]), "+f"(c[3])
        : "r"(a[0]), "r"(a[1]), "r"(a[2]), "r"(a[3]), "r"(b0), "r"(b1));
}

// ---------------------------------------------------------------------------
// Prep (merged): blocks [0, 512): attention softmax + x->fp16 (4 rows/warp,
// w_att fragment amortized). Blocks [512, 768): w -> fp16 elementwise.
// ---------------------------------------------------------------------------
__global__ __launch_bounds__(256) void prep_all(const float* __restrict__ x,
                                                const float* __restrict__ w,
                                                const float* __restrict__ w_att,
                                                const float* __restrict__ b_att) {
    if (blockIdx.x >= 512) {
        // ---- w conversion: 256 blocks * 256 threads * 4 float4 ----
        int base = (blockIdx.x - 512) * 1024 + threadIdx.x;
#pragma unroll
        for (int j = 0; j < 4; j++) {
            int i = base + j * 256;
            float4 v = ((const float4*)w)[i];
            unsigned short h0 = __half_as_ushort(__float2half_rn(v.x));
            unsigned short h1 = __half_as_ushort(__float2half_rn(v.y));
            unsigned short h2 = __half_as_ushort(__float2half_rn(v.z));
            unsigned short h3 = __half_as_ushort(__float2half_rn(v.w));
            ((uint2*)g_wh)[i] = make_uint2((uint32_t)h0 | ((uint32_t)h1 << 16),
                                           (uint32_t)h2 | ((uint32_t)h3 << 16));
        }
        return;
    }

    // ---- x + attention: each warp handles 4 rows; w_att loads amortized ----
    int warp = threadIdx.x >> 5;
    int lane = threadIdx.x & 31;
    int row0 = (blockIdx.x * 8 + warp) * 4;     // 512 blocks * 8 warps * 4 rows
    const float4* x4  = (const float4*)x;
    const float4* wa4 = (const float4*)w_att;

    float acc[4][4];
#pragma unroll
    for (int r = 0; r < 4; r++)
#pragma unroll
        for (int j = 0; j < 4; j++) acc[r][j] = 0.f;

#pragma unroll
    for (int i = 0; i < 8; i++) {
        int q = i * 32 + lane;
        float4 w0 = wa4[q * 4 + 0], w1 = wa4[q * 4 + 1];
        float4 w2 = wa4[q * 4 + 2], w3 = wa4[q * 4 + 3];
#pragma unroll
        for (int r = 0; r < 4; r++) {
            float4 v = x4[(size_t)(row0 + r) * 256 + q];
            acc[r][0] = fmaf(v.x, w0.x, fmaf(v.y, w1.x,
                        fmaf(v.z, w2.x, fmaf(v.w, w3.x, acc[r][0]))));
            acc[r][1] = fmaf(v.x, w0.y, fmaf(v.y, w1.y,
                        fmaf(v.z, w2.y, fmaf(v.w, w3.y, acc[r][1]))));
            acc[r][2] = fmaf(v.x, w0.z, fmaf(v.y, w1.z,
                        fmaf(v.z, w2.z, fmaf(v.w, w3.z, acc[r][2]))));
            acc[r][3] = fmaf(v.x, w0.w, fmaf(v.y, w1.w,
                        fmaf(v.z, w2.w, fmaf(v.w, w3.w, acc[r][3]))));
            unsigned short h0 = __half_as_ushort(__float2half_rn(v.x));
            unsigned short h1 = __half_as_ushort(__float2half_rn(v.y));
            unsigned short h2 = __half_as_ushort(__float2half_rn(v.z));
            unsigned short h3 = __half_as_ushort(__float2half_rn(v.w));
            ((uint2*)g_xh)[(size_t)(row0 + r) * 256 + q] =
                make_uint2((uint32_t)h0 | ((uint32_t)h1 << 16),
                           (uint32_t)h2 | ((uint32_t)h3 << 16));
        }
    }
#pragma unroll
    for (int r = 0; r < 4; r++)
#pragma unroll
        for (int off = 16; off; off >>= 1) {
            acc[r][0] += __shfl_xor_sync(0xffffffffu, acc[r][0], off);
            acc[r][1] += __shfl_xor_sync(0xffffffffu, acc[r][1], off);
            acc[r][2] += __shfl_xor_sync(0xffffffffu, acc[r][2], off);
            acc[r][3] += __shfl_xor_sync(0xffffffffu, acc[r][3], off);
        }
    if (lane < 4) {
        float a0 = acc[lane][0] + b_att[0];
        float a1 = acc[lane][1] + b_att[1];
        float a2 = acc[lane][2] + b_att[2];
        float a3 = acc[lane][3] + b_att[3];
        float mx = fmaxf(fmaxf(a0, a1), fmaxf(a2, a3));
        float e0 = expf(a0 - mx), e1 = expf(a1 - mx);
        float e2 = expf(a2 - mx), e3 = expf(a3 - mx);
        float inv = 1.f / (e0 + e1 + e2 + e3);
        ((float4*)g_attn)[row0 + lane] =
            make_float4(e0 * inv, e1 * inv, e2 * inv, e3 * inv);
    }
}

// ---------------------------------------------------------------------------
// Main fused GEMM: fp16 mma.sync single-term + activation/attention epilogue.
// 256 threads, 128x128 tile, 8 warps (4x2), warp tile 32x64, 2 CTAs/SM.
// ---------------------------------------------------------------------------
__device__ __forceinline__ void issue_stage(char* smem, int idx, int t,
                                            int bm, int bn) {
    int kt = idx * BKC;
    char* A = smem + SM_STAGE + (idx % NSTAGE) * STAGE_BYTES;
    char* B = A + STAGE_A_BYTES;
    // A: 128 rows x 4 chunks(16B) = 512 chunks, 2 per thread
#pragma unroll
    for (int i = 0; i < 2; i++) {
        int id  = t + i * 256;
        int row = id >> 2, cq = id & 3;
        cp16(smem_u32(A + row * (LDA * 2) + cq * 16),
             g_xh + (size_t)(bm + row) * K_TOT + kt + cq * 8);
    }
    // B: 32 rows x 16 chunks = 512 chunks, 2 per thread
#pragma unroll
    for (int i = 0; i < 2; i++) {
        int id  = t + i * 256;
        int row = id >> 4, cq = id & 15;
        cp16(smem_u32(B + row * (LDB * 2) + cq * 16),
             g_wh + (size_t)(kt + row) * N_TOT + bn + cq * 8);
    }
    cp_commit();
}

__global__ __launch_bounds__(256, 2)
void fused_gemm_hmma(const float* __restrict__ b,
                     const float* __restrict__ wf,
                     const float* __restrict__ bf,
                     float* __restrict__ out) {
    extern __shared__ char smem[];
    const int t    = threadIdx.x;
    const int wid  = t >> 5;
    const int lane = t & 31;
    const int bm   = blockIdx.y * BM;
    const int bn   = blockIdx.x * BN;
    const int m0   = (wid >> 1) * 32;    // warp M offset in tile
    const int n0   = (wid & 1) * 64;     // warp N offset in tile

    // Stage epilogue tables (256 threads)
    if (t < 128) {
        ((float4*)(smem + SM_ATTN))[t] = ((const float4*)g_attn)[bm + t];
    } else {
        int c = t - 128;
        ((float*)(smem + SM_B))[c]   = b[bn + c];
        ((float4*)(smem + SM_WF))[c] = ((const float4*)wf)[bn + c];
        ((float4*)(smem + SM_BF))[c] = ((const float4*)bf)[bn + c];
    }

    issue_stage(smem, 0, t, bm, bn);
    issue_stage(smem, 1, t, bm, bn);
    issue_stage(smem, 2, t, bm, bn);

    float c[2][8][4];
#pragma unroll
    for (int mt = 0; mt < 2; mt++)
#pragma unroll
        for (int nt = 0; nt < 8; nt++)
#pragma unroll
            for (int r = 0; r < 4; r++) c[mt][nt][r] = 0.f;

    const int lrow = lane & 15;
    const int lcol = (lane >> 4) * 8;

    for (int i = 0; i < NITER; i++) {
        cp_wait2();
        __syncthreads();   // stage i ready AND everyone done reading slot (i+3)%4
        if (i + 3 < NITER) issue_stage(smem, i + 3, t, bm, bn);

        char* A = smem + SM_STAGE + (i % NSTAGE) * STAGE_BYTES;
        char* B = A + STAGE_A_BYTES;
#pragma unroll
        for (int k0 = 0; k0 < BKC; k0 += 16) {
            uint32_t af[2][4], bb[4][4];
#pragma unroll
            for (int mt = 0; mt < 2; mt++)
                ldsm_x4(af[mt], smem_u32(A + ((m0 + mt * 16 + lrow) * LDA
                                              + k0 + lcol) * 2));
#pragma unroll
            for (int ng = 0; ng < 4; ng++)
                ldsm_x4_t(bb[ng], smem_u32(B + ((k0 + lrow) * LDB
                                                + n0 + ng * 16 + lcol) * 2));
#pragma unroll
            for (int mt = 0; mt < 2; mt++)
#pragma unroll
                for (int nt = 0; nt < 8; nt++)
                    mma_fp16(c[mt][nt], af[mt],
                             bb[nt >> 1][(nt & 1) * 2], bb[nt >> 1][(nt & 1) * 2 + 1]);
        }
    }
    __syncthreads();

    // Epilogue: bias -> per-activation affine -> activations -> attn mix
    const float*  sB  = (const float*)(smem + SM_B);
    const float4* sWF = (const float4*)(smem + SM_WF);
    const float4* sBF = (const float4*)(smem + SM_BF);
    const float4* sAT = (const float4*)(smem + SM_ATTN);
    const float inv_sqrt2 = 0.70710678118654752f;

#pragma unroll
    for (int mt = 0; mt < 2; mt++) {
#pragma unroll
        for (int half = 0; half < 2; half++) {
            int lr = m0 + mt * 16 + (lane >> 2) + half * 8;
            float4 at = sAT[lr];
            float* orow = out + (size_t)(bm + lr) * N_TOT + bn;
#pragma unroll
            for (int nt = 0; nt < 8; nt++) {
                int col0 = n0 + nt * 8 + (lane & 3) * 2;
                float2 res;
#pragma unroll
                for (int h = 0; h < 2; h++) {
                    int col = col0 + h;
                    float s = c[mt][nt][half * 2 + h] + sB[col];
                    float4 wfv = sWF[col];
                    float4 bfv = sBF[col];
                    float z0 = fmaf(s, wfv.x, bfv.x);
                    float z1 = fmaf(s, wfv.y, bfv.y);
                    float z2 = fmaf(s, wfv.z, bfv.z);
                    float z3 = fmaf(s, wfv.w, bfv.w);
                    float r0 = fmaxf(z0, 0.f);
                    float r1 = __fdividef(1.f, 1.f + __expf(-z1));
                    float r2 = 1.f - __fdividef(2.f, __expf(2.f * z2) + 1.f);
                    float r3 = 0.5f * z3 * (1.f + erff(z3 * inv_sqrt2));
                    float v = r0 * at.x + r1 * at.y + r2 * at.z + r3 * at.w;
                    if (h == 0) res.x = v; else res.y = v;
                }
                *(float2*)(orow + col0) = res;
            }
        }
    }
}

// ---------------------------------------------------------------------------
extern "C" void kernel_launch(void* const* d_in, const int* in_sizes, int n_in,
                              void* d_out, int out_size) {
    const float* x     = (const float*)d_in[0];
    const float* w     = (const float*)d_in[1];
    const float* b     = (const float*)d_in[2];
    const float* wf    = (const float*)d_in[3];
    const float* bf    = (const float*)d_in[4];
    const float* w_att = (const float*)d_in[5];
    const float* b_att = (const float*)d_in[6];
    float* out = (float*)d_out;

    cudaFuncSetAttribute(fused_gemm_hmma,
                         cudaFuncAttributeMaxDynamicSharedMemorySize, SM_TOTAL);

    prep_all<<<768, 256>>>(x, w, w_att, b_att);
    fused_gemm_hmma<<<dim3(N_TOT / BN, M_TOT / BM), 256, SM_TOTAL>>>(b, wf, bf, out);
}

// round 9
// speedup vs baseline: 5.9085x; 1.1937x over previous
#include <cuda_runtime.h>
#include <cuda_fp16.h>
#include <math.h>
#include <stdint.h>

// Shape (fixed): B=8, S=2048, D=1024, U=1024, A=4
#define M_TOT 16384
#define N_TOT 1024
#define K_TOT 1024

// GEMM tiling: fp16 mma.sync, 128 threads/CTA, CTA tile 128x128,
// warp tile 64x64 (2x2 warps), register double-buffered fragments, 2 CTAs/SM
#define BM 128
#define BN 128
#define BKC 32            // fp16 K elems per stage chunk
#define NSTAGE 4
#define NITER 32          // 1024/32

// SMEM stage layout: padded rows for conflict-free ldmatrix
#define LDA 40            // A row stride in fp16 elems (80 B)
#define LDB 136           // B row stride in fp16 elems (272 B)
#define STAGE_A_BYTES (BM * LDA * 2)      // 10240
#define STAGE_B_BYTES (BKC * LDB * 2)     // 8704
#define STAGE_BYTES   (STAGE_A_BYTES + STAGE_B_BYTES)   // 18944
#define SM_ATTN  0                         // 128 * float4 = 2048
#define SM_B     2048                      // 128 * float  = 512
#define SM_WF    2560                      // 128 * float4 = 2048
#define SM_BF    4608                      // 128 * float4 = 2048
#define SM_STAGE 6656
#define SM_TOTAL (SM_STAGE + NSTAGE * STAGE_BYTES)      // 82432 (2 CTAs/SM)

// ---------------- scratch (device globals; no allocation allowed) ----------
__device__ __half g_xh[(size_t)M_TOT * K_TOT];
__device__ __half g_wh[(size_t)K_TOT * N_TOT];   // w fp16, [K][N]
__device__ float g_attn[(size_t)M_TOT * 4];

// ---------------- helpers ---------------------------------------------------
__device__ __forceinline__ uint32_t smem_u32(const void* p) {
    return (uint32_t)__cvta_generic_to_shared(p);
}
__device__ __forceinline__ void cp16(uint32_t s, const void* g) {
    asm volatile("cp.async.cg.shared.global [%0], [%1], 16;" :: "r"(s), "l"(g));
}
__device__ __forceinline__ void cp_commit() {
    asm volatile("cp.async.commit_group;" ::: "memory");
}
__device__ __forceinline__ void cp_wait2() {
    asm volatile("cp.async.wait_group 2;" ::: "memory");
}
__device__ __forceinline__ void ldsm_x4(uint32_t* r, uint32_t a) {
    asm volatile("ldmatrix.sync.aligned.m8n8.x4.shared.b16 {%0,%1,%2,%3}, [%4];"
                 : "=r"(r[0]), "=r"(r[1]), "=r"(r[2]), "=r"(r[3]) : "r"(a));
}
__device__ __forceinline__ void ldsm_x4_t(uint32_t* r, uint32_t a) {
    asm volatile("ldmatrix.sync.aligned.m8n8.x4.trans.shared.b16 {%0,%1,%2,%3}, [%4];"
                 : "=r"(r[0]), "=r"(r[1]), "=r"(r[2]), "=r"(r[3]) : "r"(a));
}
__device__ __forceinline__ void mma_fp16(float* c, const uint32_t* a,
                                         uint32_t b0, uint32_t b1) {
    asm volatile(
        "mma.sync.aligned.m16n8k16.row.col.f32.f16.f16.f32 "
        "{%0,%1,%2,%3}, {%4,%5,%6,%7}, {%8,%9}, {%0,%1,%2,%3};"
        : "+f"(c[0]), "+f"(c[1]), "+f"(c[2]), "+f"(c[3])
        : "r"(a[0]), "r"(a[1]), "r"(a[2]), "r"(a[3]), "r"(b0), "r"(b1));
}

// ---------------------------------------------------------------------------
// Prep (merged): blocks [0, 512): attention softmax + x->fp16 (4 rows/warp,
// w_att fragment amortized). Blocks [512, 768): w -> fp16 elementwise.
// ---------------------------------------------------------------------------
__global__ __launch_bounds__(256) void prep_all(const float* __restrict__ x,
                                                const float* __restrict__ w,
                                                const float* __restrict__ w_att,
                                                const float* __restrict__ b_att) {
    if (blockIdx.x >= 512) {
        int base = (blockIdx.x - 512) * 1024 + threadIdx.x;
#pragma unroll
        for (int j = 0; j < 4; j++) {
            int i = base + j * 256;
            float4 v = ((const float4*)w)[i];
            unsigned short h0 = __half_as_ushort(__float2half_rn(v.x));
            unsigned short h1 = __half_as_ushort(__float2half_rn(v.y));
            unsigned short h2 = __half_as_ushort(__float2half_rn(v.z));
            unsigned short h3 = __half_as_ushort(__float2half_rn(v.w));
            ((uint2*)g_wh)[i] = make_uint2((uint32_t)h0 | ((uint32_t)h1 << 16),
                                           (uint32_t)h2 | ((uint32_t)h3 << 16));
        }
        return;
    }

    int warp = threadIdx.x >> 5;
    int lane = threadIdx.x & 31;
    int row0 = (blockIdx.x * 8 + warp) * 4;
    const float4* x4  = (const float4*)x;
    const float4* wa4 = (const float4*)w_att;

    float acc[4][4];
#pragma unroll
    for (int r = 0; r < 4; r++)
#pragma unroll
        for (int j = 0; j < 4; j++) acc[r][j] = 0.f;

#pragma unroll
    for (int i = 0; i < 8; i++) {
        int q = i * 32 + lane;
        float4 w0 = wa4[q * 4 + 0], w1 = wa4[q * 4 + 1];
        float4 w2 = wa4[q * 4 + 2], w3 = wa4[q * 4 + 3];
#pragma unroll
        for (int r = 0; r < 4; r++) {
            float4 v = x4[(size_t)(row0 + r) * 256 + q];
            acc[r][0] = fmaf(v.x, w0.x, fmaf(v.y, w1.x,
                        fmaf(v.z, w2.x, fmaf(v.w, w3.x, acc[r][0]))));
            acc[r][1] = fmaf(v.x, w0.y, fmaf(v.y, w1.y,
                        fmaf(v.z, w2.y, fmaf(v.w, w3.y, acc[r][1]))));
            acc[r][2] = fmaf(v.x, w0.z, fmaf(v.y, w1.z,
                        fmaf(v.z, w2.z, fmaf(v.w, w3.z, acc[r][2]))));
            acc[r][3] = fmaf(v.x, w0.w, fmaf(v.y, w1.w,
                        fmaf(v.z, w2.w, fmaf(v.w, w3.w, acc[r][3]))));
            unsigned short h0 = __half_as_ushort(__float2half_rn(v.x));
            unsigned short h1 = __half_as_ushort(__float2half_rn(v.y));
            unsigned short h2 = __half_as_ushort(__float2half_rn(v.z));
            unsigned short h3 = __half_as_ushort(__float2half_rn(v.w));
            ((uint2*)g_xh)[(size_t)(row0 + r) * 256 + q] =
                make_uint2((uint32_t)h0 | ((uint32_t)h1 << 16),
                           (uint32_t)h2 | ((uint32_t)h3 << 16));
        }
    }
#pragma unroll
    for (int r = 0; r < 4; r++)
#pragma unroll
        for (int off = 16; off; off >>= 1) {
            acc[r][0] += __shfl_xor_sync(0xffffffffu, acc[r][0], off);
            acc[r][1] += __shfl_xor_sync(0xffffffffu, acc[r][1], off);
            acc[r][2] += __shfl_xor_sync(0xffffffffu, acc[r][2], off);
            acc[r][3] += __shfl_xor_sync(0xffffffffu, acc[r][3], off);
        }
    if (lane < 4) {
        float a0 = acc[lane][0] + b_att[0];
        float a1 = acc[lane][1] + b_att[1];
        float a2 = acc[lane][2] + b_att[2];
        float a3 = acc[lane][3] + b_att[3];
        float mx = fmaxf(fmaxf(a0, a1), fmaxf(a2, a3));
        float e0 = expf(a0 - mx), e1 = expf(a1 - mx);
        float e2 = expf(a2 - mx), e3 = expf(a3 - mx);
        float inv = 1.f / (e0 + e1 + e2 + e3);
        ((float4*)g_attn)[row0 + lane] =
            make_float4(e0 * inv, e1 * inv, e2 * inv, e3 * inv);
    }
}

// ---------------------------------------------------------------------------
// Main fused GEMM: fp16 mma.sync, warp tile 64x64, reg-double-buffered frags.
// 128 threads, 4 warps (2x2), 2 CTAs/SM.
// ---------------------------------------------------------------------------
__device__ __forceinline__ void issue_stage(char* smem, int idx, int t,
                                            int bm, int bn) {
    int kt = idx * BKC;
    char* A = smem + SM_STAGE + (idx % NSTAGE) * STAGE_BYTES;
    char* B = A + STAGE_A_BYTES;
    // A: 128 rows x 4 chunks(16B) = 512 chunks, 4 per thread
#pragma unroll
    for (int i = 0; i < 4; i++) {
        int id  = t + i * 128;
        int row = id >> 2, cq = id & 3;
        cp16(smem_u32(A + row * (LDA * 2) + cq * 16),
             g_xh + (size_t)(bm + row) * K_TOT + kt + cq * 8);
    }
    // B: 32 rows x 16 chunks = 512 chunks, 4 per thread
#pragma unroll
    for (int i = 0; i < 4; i++) {
        int id  = t + i * 128;
        int row = id >> 4, cq = id & 15;
        cp16(smem_u32(B + row * (LDB * 2) + cq * 16),
             g_wh + (size_t)(kt + row) * N_TOT + bn + cq * 8);
    }
    cp_commit();
}

__global__ __launch_bounds__(128, 2)
void fused_gemm_hmma(const float* __restrict__ b,
                     const float* __restrict__ wf,
                     const float* __restrict__ bf,
                     float* __restrict__ out) {
    extern __shared__ char smem[];
    const int t    = threadIdx.x;
    const int wid  = t >> 5;
    const int lane = t & 31;
    const int bm   = blockIdx.y * BM;
    const int bn   = blockIdx.x * BN;
    const int m0   = (wid >> 1) * 64;    // warp M offset
    const int n0   = (wid & 1) * 64;     // warp N offset

    // Stage epilogue tables (128 threads)
    ((float4*)(smem + SM_ATTN))[t] = ((const float4*)g_attn)[bm + t];
    ((float*)(smem + SM_B))[t]     = b[bn + t];
    ((float4*)(smem + SM_WF))[t]   = ((const float4*)wf)[bn + t];
    ((float4*)(smem + SM_BF))[t]   = ((const float4*)bf)[bn + t];

    issue_stage(smem, 0, t, bm, bn);
    issue_stage(smem, 1, t, bm, bn);
    issue_stage(smem, 2, t, bm, bn);

    float c[4][8][4];
#pragma unroll
    for (int mt = 0; mt < 4; mt++)
#pragma unroll
        for (int nt = 0; nt < 8; nt++)
#pragma unroll
            for (int r = 0; r < 4; r++) c[mt][nt][r] = 0.f;

    const int lrow = lane & 15;
    const int lcol = (lane >> 4) * 8;

    // Fragment double buffers: A 4x4 regs, B 4x4 regs per buffer
    uint32_t af[2][4][4], bb[2][4][4];

#define LDFRAG(buf, Aptr, Bptr, k0)                                           \
    do {                                                                      \
        _Pragma("unroll")                                                     \
        for (int mt = 0; mt < 4; mt++)                                        \
            ldsm_x4(af[buf][mt], smem_u32((Aptr) +                            \
                    ((m0 + mt * 16 + lrow) * LDA + (k0) + lcol) * 2));        \
        _Pragma("unroll")                                                     \
        for (int ng = 0; ng < 4; ng++)                                        \
            ldsm_x4_t(bb[buf][ng], smem_u32((Bptr) +                          \
                    (((k0) + lrow) * LDB + n0 + ng * 16 + lcol) * 2));        \
    } while (0)

#define MMA_ALL(buf)                                                          \
    do {                                                                      \
        _Pragma("unroll")                                                     \
        for (int mt = 0; mt < 4; mt++)                                        \
            _Pragma("unroll")                                                 \
            for (int nt = 0; nt < 8; nt++)                                    \
                mma_fp16(c[mt][nt], af[buf][mt],                              \
                         bb[buf][nt >> 1][(nt & 1) * 2],                      \
                         bb[buf][nt >> 1][(nt & 1) * 2 + 1]);                 \
    } while (0)

    cp_wait2();
    __syncthreads();
    {
        char* A0 = smem + SM_STAGE;
        LDFRAG(0, A0, A0 + STAGE_A_BYTES, 0);
    }

    for (int i = 0; i < NITER; i++) {
        char* A = smem + SM_STAGE + (i % NSTAGE) * STAGE_BYTES;
        char* B = A + STAGE_A_BYTES;

        LDFRAG(1, A, B, 16);          // this chunk's k-group 1 (prefetch)
        MMA_ALL(0);                   // k-group 0

        if (i + 3 < NITER) issue_stage(smem, i + 3, t, bm, bn);
        cp_wait2();
        __syncthreads();              // stage i+1 ready; stage (i-1) reads done

        if (i + 1 < NITER) {
            char* An = smem + SM_STAGE + ((i + 1) % NSTAGE) * STAGE_BYTES;
            LDFRAG(0, An, An + STAGE_A_BYTES, 0);   // next chunk's k-group 0
        }
        MMA_ALL(1);                   // k-group 1
    }

    // Epilogue: bias -> per-activation affine -> activations -> attn mix
    const float*  sB  = (const float*)(smem + SM_B);
    const float4* sWF = (const float4*)(smem + SM_WF);
    const float4* sBF = (const float4*)(smem + SM_BF);
    const float4* sAT = (const float4*)(smem + SM_ATTN);
    const float inv_sqrt2 = 0.70710678118654752f;

#pragma unroll
    for (int mt = 0; mt < 4; mt++) {
#pragma unroll
        for (int half = 0; half < 2; half++) {
            int lr = m0 + mt * 16 + (lane >> 2) + half * 8;
            float4 at = sAT[lr];
            float* orow = out + (size_t)(bm + lr) * N_TOT + bn;
#pragma unroll
            for (int nt = 0; nt < 8; nt++) {
                int col0 = n0 + nt * 8 + (lane & 3) * 2;
                float2 res;
#pragma unroll
                for (int h = 0; h < 2; h++) {
                    int col = col0 + h;
                    float s = c[mt][nt][half * 2 + h] + sB[col];
                    float4 wfv = sWF[col];
                    float4 bfv = sBF[col];
                    float z0 = fmaf(s, wfv.x, bfv.x);
                    float z1 = fmaf(s, wfv.y, bfv.y);
                    float z2 = fmaf(s, wfv.z, bfv.z);
                    float z3 = fmaf(s, wfv.w, bfv.w);
                    float r0 = fmaxf(z0, 0.f);
                    float r1 = __fdividef(1.f, 1.f + __expf(-z1));
                    float r2 = 1.f - __fdividef(2.f, __expf(2.f * z2) + 1.f);
                    float r3 = 0.5f * z3 * (1.f + erff(z3 * inv_sqrt2));
                    float v = r0 * at.x + r1 * at.y + r2 * at.z + r3 * at.w;
                    if (h == 0) res.x = v; else res.y = v;
                }
                *(float2*)(orow + col0) = res;
            }
        }
    }
}

// ---------------------------------------------------------------------------
extern "C" void kernel_launch(void* const* d_in, const int* in_sizes, int n_in,
                              void* d_out, int out_size) {
    const float* x     = (const float*)d_in[0];
    const float* w     = (const float*)d_in[1];
    const float* b     = (const float*)d_in[2];
    const float* wf    = (const float*)d_in[3];
    const float* bf    = (const float*)d_in[4];
    const float* w_att = (const float*)d_in[5];
    const float* b_att = (const float*)d_in[6];
    float* out = (float*)d_out;

    cudaFuncSetAttribute(fused_gemm_hmma,
                         cudaFuncAttributeMaxDynamicSharedMemorySize, SM_TOTAL);

    prep_all<<<768, 256>>>(x, w, w_att, b_att);
    fused_gemm_hmma<<<dim3(N_TOT / BN, M_TOT / BM), 128, SM_TOTAL>>>(b, wf, bf, out);
}